// round 10
// baseline (speedup 1.0000x reference)
#include <cuda_runtime.h>
#include <cuda_bf16.h>
#include <stdint.h>
#include <math.h>

#define T    512
#define H    2048
#define II   1024
#define E    64
#define KSEL 8

#define BM   64
#define BK   32
#define PADK 40                      // padded k-stride (elems): 80B, 16B-aligned, ldmatrix conflict-free
#define NSTAGE 3

// stage = 15360 bf16 elems = 30720 B; three stages.
#define STG_ELEMS 15360
#define META_OFF  (NSTAGE * STG_ELEMS * 2)     // 92160 B
#define BAR_OFF   (META_OFF + 1024)
#define SMEM_DYN  (BAR_OFF + 64)

// gateup regions (elem offsets within a stage)
#define GA_HI 0
#define GA_LO 2560
#define GG_HI 5120
#define GG_LO 7680
#define GU_HI 10240
#define GU_LO 12800
// down regions: A 64x40 hi/lo, B 128x40 hi/lo
#define DA_HI 0
#define DA_LO 2560
#define DB_HI 5120
#define DB_LO 10240

// -------- device-global scratch (no allocations allowed) --------
__device__ int   g_cnt[E];
__device__ int   g_off[E];
__device__ int   g_tok[E * T];
__device__ float g_prob[E * T];
__device__ float g_act[(size_t)T * KSEL * II];

// ======================= helpers =======================
__device__ __forceinline__ uint32_t smem_u32(const void* p) {
    uint32_t a;
    asm("{ .reg .u64 t; cvta.to.shared.u64 t, %1; cvt.u32.u64 %0, t; }" : "=r"(a) : "l"(p));
    return a;
}

#define MBARRIER_INIT(addr, cnt) \
    asm volatile("mbarrier.init.shared.b64 [%0], %1;" :: "r"((uint32_t)(addr)), "r"((uint32_t)(cnt)) : "memory")
#define MBARRIER_ARRIVE(addr) \
    asm volatile("mbarrier.arrive.shared.b64 _, [%0];" :: "r"((uint32_t)(addr)) : "memory")

#define MBARRIER_WAIT_PARITY(addr, par) do { \
    uint32_t _mb = (uint32_t)(addr); uint32_t _p = (uint32_t)(par); uint32_t _d; \
    asm volatile("{\n\t.reg .pred p;\n\t" \
        "mbarrier.try_wait.parity.acquire.cta.shared::cta.b64 p, [%1], %2;\n\t" \
        "selp.b32 %0, 1, 0, p;\n\t}" : "=r"(_d) : "r"(_mb), "r"(_p) : "memory"); \
    if (!_d) { \
        asm volatile("{\n\t.reg .pred P1;\n\t" \
            "WL_%=:\n\t" \
            "mbarrier.try_wait.parity.acquire.cta.shared::cta.b64 P1, [%0], %1, 0x989680;\n\t" \
            "@P1 bra.uni WD_%=;\n\t" \
            "bra.uni WL_%=;\n\t" \
            "WD_%=:\n\t}" :: "r"(_mb), "r"(_p) : "memory"); \
    } \
} while (0)

__device__ __forceinline__ void ldm_x4(uint32_t r[4], uint32_t addr) {
    asm volatile("ldmatrix.sync.aligned.m8n8.x4.shared.b16 {%0,%1,%2,%3}, [%4];"
                 : "=r"(r[0]), "=r"(r[1]), "=r"(r[2]), "=r"(r[3]) : "r"(addr));
}
__device__ __forceinline__ void mma_bf16(float d[4], const uint32_t a[4], const uint32_t b0, const uint32_t b1) {
    asm volatile("mma.sync.aligned.m16n8k16.row.col.f32.bf16.bf16.f32 "
                 "{%0,%1,%2,%3}, {%4,%5,%6,%7}, {%8,%9}, {%0,%1,%2,%3};"
                 : "+f"(d[0]), "+f"(d[1]), "+f"(d[2]), "+f"(d[3])
                 : "r"(a[0]), "r"(a[1]), "r"(a[2]), "r"(a[3]), "r"(b0), "r"(b1));
}

// split fp32x4 -> bf16 hi/lo, store 8B each
__device__ __forceinline__ void split_sts(__nv_bfloat16* hi, __nv_bfloat16* lo, float4 v) {
    __nv_bfloat16 h0 = __float2bfloat16(v.x), h1 = __float2bfloat16(v.y);
    __nv_bfloat16 h2 = __float2bfloat16(v.z), h3 = __float2bfloat16(v.w);
    __nv_bfloat16 l0 = __float2bfloat16(v.x - __bfloat162float(h0));
    __nv_bfloat16 l1 = __float2bfloat16(v.y - __bfloat162float(h1));
    __nv_bfloat16 l2 = __float2bfloat16(v.z - __bfloat162float(h2));
    __nv_bfloat16 l3 = __float2bfloat16(v.w - __bfloat162float(h3));
    uint2 hp, lp;
    hp.x = (uint32_t)__bfloat16_as_ushort(h0) | ((uint32_t)__bfloat16_as_ushort(h1) << 16);
    hp.y = (uint32_t)__bfloat16_as_ushort(h2) | ((uint32_t)__bfloat16_as_ushort(h3) << 16);
    lp.x = (uint32_t)__bfloat16_as_ushort(l0) | ((uint32_t)__bfloat16_as_ushort(l1) << 16);
    lp.y = (uint32_t)__bfloat16_as_ushort(l2) | ((uint32_t)__bfloat16_as_ushort(l3) << 16);
    *(uint2*)hi = hp;
    *(uint2*)lo = lp;
}

// ======================= gating =======================
__global__ void gate_kernel(const float* __restrict__ x,
                            const float* __restrict__ Wgate)
{
    __shared__ float sx[H];
    __shared__ float slog[E];
    __shared__ int   s_ids[KSEL];
    __shared__ float s_p[KSEL];

    const int t = blockIdx.x, tid = threadIdx.x;
    for (int i = tid; i < H; i += blockDim.x) sx[i] = x[(size_t)t * H + i];
    __syncthreads();

    const int w = tid >> 5, lane = tid & 31;
    for (int j = 0; j < 8; j++) {
        const int e = w * 8 + j;
        const float* wr = Wgate + (size_t)e * H;
        float s = 0.f;
        for (int h = lane; h < H; h += 32) s += sx[h] * wr[h];
        #pragma unroll
        for (int o = 16; o > 0; o >>= 1) s += __shfl_xor_sync(0xffffffffu, s, o);
        if (lane == 0) slog[e] = s;
    }
    __syncthreads();

    if (tid == 0) {
        float vals[KSEL]; int ids[KSEL];
        for (int j = 0; j < KSEL; j++) {
            float best = -1e30f; int bi = 0;
            for (int e = 0; e < E; e++)
                if (slog[e] > best) { best = slog[e]; bi = e; }
            vals[j] = best; ids[j] = bi; slog[bi] = -1e30f;
        }
        const float m = vals[0];
        float sum = 0.f;
        for (int j = 0; j < KSEL; j++) { vals[j] = expf(vals[j] - m); sum += vals[j]; }
        const float inv = 1.f / sum;
        for (int j = 0; j < KSEL; j++) { s_ids[j] = ids[j]; s_p[j] = vals[j] * inv; }
    }
    __syncthreads();

    if (tid < KSEL) {
        const int e = s_ids[tid];
        const int pos = atomicAdd(&g_cnt[e], 1);
        g_tok[e * T + pos]  = t;
        g_prob[e * T + pos] = s_p[tid];
    }
}

__global__ void scan_kernel()
{
    if (threadIdx.x == 0) {
        int s = 0;
        for (int e = 0; e < E; e++) { g_off[e] = s; s += g_cnt[e]; }
    }
}

// ======================= gate/up: warp-specialized mma.sync + SwiGLU =======================
// 384 threads: warps 0-7 consumers (2m x 4n, 32m x 16i x {g,u}), warps 8-11 producers.
__global__ __launch_bounds__(384, 2) void gateup_mma(const float* __restrict__ x,
                                                     const float* __restrict__ Wg,
                                                     const float* __restrict__ Wu)
{
    extern __shared__ __align__(16) char smraw[];
    __nv_bfloat16* sm = (__nv_bfloat16*)smraw;

    const int e   = blockIdx.z;
    const int cnt = g_cnt[e];
    const int m0  = blockIdx.y * BM;
    if (m0 >= cnt) return;
    const int i0   = blockIdx.x * 64;
    const int base = g_off[e];
    const int tid = threadIdx.x, wid = tid >> 5, lane = tid & 31;
    const uint32_t sb  = smem_u32(smraw);
    const uint32_t bar = sb + BAR_OFF;     // full[s]=bar+s*16, empty[s]=bar+s*16+8

    int*   stok = (int*)(smraw + META_OFF);
    float* sp   = (float*)(smraw + META_OFF + 512);
    if (tid < BM) {
        const int mm = min(m0 + tid, cnt - 1);
        stok[tid] = g_tok[e * T + mm];
        sp[tid]   = (m0 + tid < cnt) ? g_prob[e * T + m0 + tid] : 0.f;
    }
    if (tid == 0) {
        #pragma unroll
        for (int s = 0; s < NSTAGE; s++) {
            MBARRIER_INIT(bar + s * 16,     128);   // full: 128 producer arrivals
            MBARRIER_INIT(bar + s * 16 + 8, 256);   // empty: 256 consumer arrivals
        }
    }
    __syncthreads();

    const float* WgE = Wg + ((size_t)e * II + i0) * H;
    const float* WuE = Wu + ((size_t)e * II + i0) * H;
    const int NCH = H / BK;    // 64

    if (wid >= 8) {
        // ---------------- producers ----------------
        const int ptid = tid - 256;
        const int rr = ptid >> 3, cc = (ptid & 7) * 4;
        const float* pA[4]; const float* pG[4]; const float* pU[4];
        int offj[4];
        #pragma unroll
        for (int j = 0; j < 4; j++) {
            const int r = rr + j * 16;
            pA[j] = x + (size_t)stok[r] * H + cc;
            pG[j] = WgE + (size_t)r * H + cc;
            pU[j] = WuE + (size_t)r * H + cc;
            offj[j] = r * PADK + cc;
        }
        int ps = 0, pph = 1;
        for (int ch = 0; ch < NCH; ch++) {
            MBARRIER_WAIT_PARITY(bar + ps * 16 + 8, pph);
            __nv_bfloat16* s = sm + ps * STG_ELEMS;
            const int k0 = ch * BK;
            float4 v[4];
            #pragma unroll
            for (int j = 0; j < 4; j++) v[j] = *(const float4*)(pA[j] + k0);
            #pragma unroll
            for (int j = 0; j < 4; j++) split_sts(s + GA_HI + offj[j], s + GA_LO + offj[j], v[j]);
            #pragma unroll
            for (int j = 0; j < 4; j++) v[j] = *(const float4*)(pG[j] + k0);
            #pragma unroll
            for (int j = 0; j < 4; j++) split_sts(s + GG_HI + offj[j], s + GG_LO + offj[j], v[j]);
            #pragma unroll
            for (int j = 0; j < 4; j++) v[j] = *(const float4*)(pU[j] + k0);
            #pragma unroll
            for (int j = 0; j < 4; j++) split_sts(s + GU_HI + offj[j], s + GU_LO + offj[j], v[j]);
            MBARRIER_ARRIVE(bar + ps * 16);
            if (++ps == NSTAGE) { ps = 0; pph ^= 1; }
        }
    } else {
        // ---------------- consumers ----------------
        const int wm = wid >> 2;   // 0..1
        const int wn = wid & 3;    // 0..3
        const uint32_t offA0 = (uint32_t)((wm * 32 + (lane & 15)) * PADK + ((lane >> 4) << 3));
        const uint32_t offA1 = offA0 + 16 * PADK;
        const uint32_t offB  = (uint32_t)((wn * 16 + ((lane >> 4) << 3) + (lane & 7)) * PADK
                                          + (((lane >> 3) & 1) << 3));
        float ag[2][2][4] = {}, au[2][2][4] = {};
        int cs = 0, cph = 0;
        for (int ch = 0; ch < NCH; ch++) {
            MBARRIER_WAIT_PARITY(bar + cs * 16, cph);
            const uint32_t sbase = sb + (uint32_t)cs * (STG_ELEMS * 2);
            #pragma unroll
            for (int k16 = 0; k16 < BK; k16 += 16) {
                const uint32_t kb = (uint32_t)k16 * 2;
                uint32_t ah[2][4], al[2][4];
                ldm_x4(ah[0], sbase + (GA_HI * 2) + (offA0 * 2) + kb);
                ldm_x4(al[0], sbase + (GA_LO * 2) + (offA0 * 2) + kb);
                ldm_x4(ah[1], sbase + (GA_HI * 2) + (offA1 * 2) + kb);
                ldm_x4(al[1], sbase + (GA_LO * 2) + (offA1 * 2) + kb);
                uint32_t gh[4], gl[4], uh[4], ul[4];
                ldm_x4(gh, sbase + (GG_HI * 2) + (offB * 2) + kb);
                ldm_x4(gl, sbase + (GG_LO * 2) + (offB * 2) + kb);
                ldm_x4(uh, sbase + (GU_HI * 2) + (offB * 2) + kb);
                ldm_x4(ul, sbase + (GU_LO * 2) + (offB * 2) + kb);
                #pragma unroll
                for (int mt = 0; mt < 2; mt++) {
                    #pragma unroll
                    for (int it = 0; it < 2; it++) {
                        mma_bf16(ag[mt][it], ah[mt], gh[it * 2], gh[it * 2 + 1]);
                        mma_bf16(ag[mt][it], ah[mt], gl[it * 2], gl[it * 2 + 1]);
                        mma_bf16(ag[mt][it], al[mt], gh[it * 2], gh[it * 2 + 1]);
                        mma_bf16(au[mt][it], ah[mt], uh[it * 2], uh[it * 2 + 1]);
                        mma_bf16(au[mt][it], ah[mt], ul[it * 2], ul[it * 2 + 1]);
                        mma_bf16(au[mt][it], al[mt], uh[it * 2], uh[it * 2 + 1]);
                    }
                }
            }
            MBARRIER_ARRIVE(bar + cs * 16 + 8);
            if (++cs == NSTAGE) { cs = 0; cph ^= 1; }
        }

        // epilogue: silu(hg)*hu*p -> g_act
        #pragma unroll
        for (int mt = 0; mt < 2; mt++) {
            #pragma unroll
            for (int it = 0; it < 2; it++) {
                const int c  = i0 + wn * 16 + it * 8 + (lane & 3) * 2;
                const int r0 = wm * 32 + mt * 16 + (lane >> 2);
                #pragma unroll
                for (int hf = 0; hf < 2; hf++) {
                    const int r = r0 + hf * 8;
                    if (m0 + r < cnt) {
                        const float p = sp[r];
                        const float hg0 = ag[mt][it][hf * 2 + 0], hu0 = au[mt][it][hf * 2 + 0];
                        const float hg1 = ag[mt][it][hf * 2 + 1], hu1 = au[mt][it][hf * 2 + 1];
                        float2 v;
                        v.x = hg0 / (1.f + expf(-hg0)) * hu0 * p;
                        v.y = hg1 / (1.f + expf(-hg1)) * hu1 * p;
                        *(float2*)(g_act + (size_t)(base + m0 + r) * II + c) = v;
                    }
                }
            }
        }
    }
}

// ======================= down: warp-specialized mma.sync + scatter =======================
// 384 threads: warps 0-7 consumers (2m x 4n, 32m x 32n), warps 8-11 producers.
__global__ __launch_bounds__(384, 2) void down_mma(const float* __restrict__ Wd,
                                                   float* __restrict__ out)
{
    extern __shared__ __align__(16) char smraw[];
    __nv_bfloat16* sm = (__nv_bfloat16*)smraw;

    const int e   = blockIdx.z;
    const int cnt = g_cnt[e];
    const int m0  = blockIdx.y * BM;
    if (m0 >= cnt) return;
    const int n0   = blockIdx.x * 128;
    const int base = g_off[e];
    const int tid = threadIdx.x, wid = tid >> 5, lane = tid & 31;
    const uint32_t sb  = smem_u32(smraw);
    const uint32_t bar = sb + BAR_OFF;

    int* stok = (int*)(smraw + META_OFF);
    int* srow = (int*)(smraw + META_OFF + 512);
    if (tid < BM) {
        const int mm = min(m0 + tid, cnt - 1);
        stok[tid] = g_tok[e * T + mm];
        srow[tid] = base + mm;
    }
    if (tid == 0) {
        #pragma unroll
        for (int s = 0; s < NSTAGE; s++) {
            MBARRIER_INIT(bar + s * 16,     128);
            MBARRIER_INIT(bar + s * 16 + 8, 256);
        }
    }
    __syncthreads();

    const float* WdE = Wd + ((size_t)e * H + n0) * II;
    const int NCH = II / BK;   // 32

    if (wid >= 8) {
        // ---------------- producers ----------------
        const int ptid = tid - 256;
        const int rr = ptid >> 3, cc = (ptid & 7) * 4;
        const float* pA[4]; const float* pB[8];
        int offjA[4], offjB[8];
        #pragma unroll
        for (int j = 0; j < 4; j++) {
            const int r = rr + j * 16;
            pA[j] = g_act + (size_t)srow[r] * II + cc;
            offjA[j] = r * PADK + cc;
        }
        #pragma unroll
        for (int j = 0; j < 8; j++) {
            const int r = rr + j * 16;
            pB[j] = WdE + (size_t)r * II + cc;
            offjB[j] = r * PADK + cc;
        }
        int ps = 0, pph = 1;
        for (int ch = 0; ch < NCH; ch++) {
            MBARRIER_WAIT_PARITY(bar + ps * 16 + 8, pph);
            __nv_bfloat16* s = sm + ps * STG_ELEMS;
            const int k0 = ch * BK;
            float4 v[4];
            #pragma unroll
            for (int j = 0; j < 4; j++) v[j] = *(const float4*)(pA[j] + k0);
            #pragma unroll
            for (int j = 0; j < 4; j++) split_sts(s + DA_HI + offjA[j], s + DA_LO + offjA[j], v[j]);
            #pragma unroll
            for (int j = 0; j < 4; j++) v[j] = *(const float4*)(pB[j] + k0);
            #pragma unroll
            for (int j = 0; j < 4; j++) split_sts(s + DB_HI + offjB[j], s + DB_LO + offjB[j], v[j]);
            #pragma unroll
            for (int j = 0; j < 4; j++) v[j] = *(const float4*)(pB[j + 4] + k0);
            #pragma unroll
            for (int j = 0; j < 4; j++) split_sts(s + DB_HI + offjB[j + 4], s + DB_LO + offjB[j + 4], v[j]);
            MBARRIER_ARRIVE(bar + ps * 16);
            if (++ps == NSTAGE) { ps = 0; pph ^= 1; }
        }
    } else {
        // ---------------- consumers ----------------
        const int wm = wid >> 2;   // 0..1
        const int wn = wid & 3;    // 0..3
        const uint32_t offA0 = (uint32_t)((wm * 32 + (lane & 15)) * PADK + ((lane >> 4) << 3));
        const uint32_t offA1 = offA0 + 16 * PADK;
        const uint32_t offB0 = (uint32_t)((wn * 32 + ((lane >> 4) << 3) + (lane & 7)) * PADK
                                          + (((lane >> 3) & 1) << 3));
        const uint32_t offB1 = offB0 + 16 * PADK;
        float acc[2][4][4] = {};
        int cs = 0, cph = 0;
        for (int ch = 0; ch < NCH; ch++) {
            MBARRIER_WAIT_PARITY(bar + cs * 16, cph);
            const uint32_t sbase = sb + (uint32_t)cs * (STG_ELEMS * 2);
            #pragma unroll
            for (int k16 = 0; k16 < BK; k16 += 16) {
                const uint32_t kb = (uint32_t)k16 * 2;
                uint32_t ah[2][4], al[2][4];
                ldm_x4(ah[0], sbase + (DA_HI * 2) + (offA0 * 2) + kb);
                ldm_x4(al[0], sbase + (DA_LO * 2) + (offA0 * 2) + kb);
                ldm_x4(ah[1], sbase + (DA_HI * 2) + (offA1 * 2) + kb);
                ldm_x4(al[1], sbase + (DA_LO * 2) + (offA1 * 2) + kb);
                uint32_t bh[2][4], bl[2][4];
                ldm_x4(bh[0], sbase + (DB_HI * 2) + (offB0 * 2) + kb);
                ldm_x4(bl[0], sbase + (DB_LO * 2) + (offB0 * 2) + kb);
                ldm_x4(bh[1], sbase + (DB_HI * 2) + (offB1 * 2) + kb);
                ldm_x4(bl[1], sbase + (DB_LO * 2) + (offB1 * 2) + kb);
                #pragma unroll
                for (int mt = 0; mt < 2; mt++) {
                    #pragma unroll
                    for (int nt = 0; nt < 4; nt++) {
                        const int p = nt >> 1, q = (nt & 1) * 2;
                        mma_bf16(acc[mt][nt], ah[mt], bh[p][q], bh[p][q + 1]);
                        mma_bf16(acc[mt][nt], ah[mt], bl[p][q], bl[p][q + 1]);
                        mma_bf16(acc[mt][nt], al[mt], bh[p][q], bh[p][q + 1]);
                    }
                }
            }
            MBARRIER_ARRIVE(bar + cs * 16 + 8);
            if (++cs == NSTAGE) { cs = 0; cph ^= 1; }
        }

        // epilogue: atomic scatter into out
        #pragma unroll
        for (int mt = 0; mt < 2; mt++) {
            #pragma unroll
            for (int nt = 0; nt < 4; nt++) {
                const int c  = n0 + wn * 32 + nt * 8 + (lane & 3) * 2;
                const int r0 = wm * 32 + mt * 16 + (lane >> 2);
                #pragma unroll
                for (int hf = 0; hf < 2; hf++) {
                    const int r = r0 + hf * 8;
                    if (m0 + r < cnt) {
                        float* orow = out + (size_t)stok[r] * H + c;
                        atomicAdd(&orow[0], acc[mt][nt][hf * 2 + 0]);
                        atomicAdd(&orow[1], acc[mt][nt][hf * 2 + 1]);
                    }
                }
            }
        }
    }
}

// ======================= launch =======================
extern "C" void kernel_launch(void* const* d_in, const int* in_sizes, int n_in,
                              void* d_out, int out_size)
{
    const float* x     = (const float*)d_in[0];
    const float* Wg    = (const float*)d_in[1];
    const float* Wu    = (const float*)d_in[2];
    const float* Wd    = (const float*)d_in[3];
    const float* Wgate = (const float*)d_in[4];
    float* out = (float*)d_out;

    cudaFuncSetAttribute(gateup_mma, cudaFuncAttributeMaxDynamicSharedMemorySize, SMEM_DYN);
    cudaFuncSetAttribute(down_mma,   cudaFuncAttributeMaxDynamicSharedMemorySize, SMEM_DYN);

    void* cnt_ptr = nullptr;
    cudaGetSymbolAddress(&cnt_ptr, g_cnt);
    cudaMemsetAsync(cnt_ptr, 0, E * sizeof(int));
    cudaMemsetAsync(d_out, 0, (size_t)T * H * sizeof(float));

    gate_kernel<<<T, 256>>>(x, Wgate);
    scan_kernel<<<1, 32>>>();

    dim3 g1(II / 64, T / BM, E);     // 16 x 8 x 64
    gateup_mma<<<g1, 384, SMEM_DYN>>>(x, Wg, Wu);

    dim3 g2(H / 128, T / BM, E);     // 16 x 8 x 64
    down_mma<<<g2, 384, SMEM_DYN>>>(Wd, out);
}